// round 4
// baseline (speedup 1.0000x reference)
#include <cuda_runtime.h>
#include <math.h>

// EntropyLoss: x [R=65536, C=1024] f32 row-major.
//   n_j  = max( sqrt(sum_i x_ij^2), 1e-12 )
//   out  = -(1/R) * sum_j (1/n_j) * [ sum_i x*ln(x) - ln(n_j) * sum_i x ]
// (eps=1e-8 inside the reference log contributes <1e-6 relative error; dropped)
//
// Single fused launch:
//   - each block accumulates per-column {sum x^2, sum x, sum x*log2(x)} over its
//     row-slices, smem-reduces 4 slices, atomicAdds into g_part
//   - last block (counter) combines columns -> scalar, writes d_out, re-zeros
//     scratch so every graph replay starts from a clean state (globals are
//     zero-init at module load, and each call leaves them zeroed).

#define COLS 1024
#define GRID_X 296          // row-chunks
#define GRID_Y 4            // column tiles of 256
#define NBLOCKS (GRID_X * GRID_Y)
#define LN2 0.6931471805599453f

__device__ float g_part[3][COLS];      // [0]=sum x^2, [1]=sum x, [2]=sum x*log2(x)
__device__ unsigned int g_count;

__global__ __launch_bounds__(256) void el_fused_kernel(const float* __restrict__ x,
                                                       float* __restrict__ out,
                                                       int rows) {
    const int tid     = threadIdx.x;
    const int cg      = tid & 63;     // 64 float4 column-groups per block (256 cols)
    const int slice   = tid >> 6;     // 4 row slices per block
    const int colbase = blockIdx.y * 256;
    const int g4      = (colbase >> 2) + cg;   // float4 index within a row

    const float4* __restrict__ p = (const float4*)x;

    float s2[4] = {0.f, 0.f, 0.f, 0.f};
    float s1[4] = {0.f, 0.f, 0.f, 0.f};
    float sx[4] = {0.f, 0.f, 0.f, 0.f};

    const int  rstride = GRID_X * 4;                 // 1184 row slices total
    const int  r0      = blockIdx.x * 4 + slice;
    const long step    = (long)rstride * (COLS / 4); // float4 stride between my rows
    const float4* __restrict__ q = p + (long)r0 * (COLS / 4) + g4;

    const int iters = (rows - r0 + rstride - 1) / rstride;
    const int nb    = iters >> 3;

    for (int b = 0; b < nb; b++) {
        float4 v[8];
        #pragma unroll
        for (int u = 0; u < 8; u++) v[u] = __ldcs(&q[(long)u * step]);
        q += 8 * step;
        #pragma unroll
        for (int u = 0; u < 8; u++) {
            float vv[4] = {v[u].x, v[u].y, v[u].z, v[u].w};
            #pragma unroll
            for (int k = 0; k < 4; k++) {
                float a = vv[k];
                s2[k] = fmaf(a, a, s2[k]);
                s1[k] += a;
                float l = __log2f(fmaxf(a, 1e-37f));   // a==0 -> fmaf(0,*,s)==s
                sx[k] = fmaf(a, l, sx[k]);
            }
        }
    }
    for (int i = nb * 8; i < iters; i++) {
        float4 v = __ldcs(q);
        q += step;
        float vv[4] = {v.x, v.y, v.z, v.w};
        #pragma unroll
        for (int k = 0; k < 4; k++) {
            float a = vv[k];
            s2[k] = fmaf(a, a, s2[k]);
            s1[k] += a;
            float l = __log2f(fmaxf(a, 1e-37f));
            sx[k] = fmaf(a, l, sx[k]);
        }
    }

    // Reduce the 4 row-slices within the block before touching L2 atomics.
    __shared__ float red[4][64 * 12];
    #pragma unroll
    for (int k = 0; k < 4; k++) {
        red[slice][cg * 12 + 0 + k] = s2[k];
        red[slice][cg * 12 + 4 + k] = s1[k];
        red[slice][cg * 12 + 8 + k] = sx[k];
    }
    __syncthreads();

    for (int i = tid; i < 64 * 12; i += 256) {
        float t = red[0][i] + red[1][i] + red[2][i] + red[3][i];
        int cg2  = i / 12;
        int comp = i % 12;
        int type = comp >> 2;     // 0: x^2, 1: x, 2: x*log2(x)
        int sub  = comp & 3;
        int col  = colbase + cg2 * 4 + sub;
        atomicAdd(&g_part[type][col], t);
    }

    // ---- last block does the final combine ----
    __shared__ int amLast;
    __threadfence();
    __syncthreads();
    if (tid == 0) {
        unsigned v = atomicAdd(&g_count, 1u);
        amLast = (v == NBLOCKS - 1);
    }
    __syncthreads();
    if (!amLast) return;

    // 256 threads over 1024 columns (4 each), L2 reads (bypass possibly-stale L1)
    float acc = 0.f;
    #pragma unroll
    for (int m = 0; m < 4; m++) {
        int j  = tid + m * 256;
        float S2 = __ldcg(&g_part[0][j]);
        float S1 = __ldcg(&g_part[1][j]);
        float SX = __ldcg(&g_part[2][j]);
        float n  = fmaxf(sqrtf(S2), 1e-12f);
        acc += (SX * LN2 - S1 * logf(n)) / n;
    }

    // re-zero scratch for the next replay (each thread zeros exactly the
    // flat indices it just read: tid + 256*k, k=0..11)
    for (int i = tid; i < 3 * COLS; i += 256) ((float*)g_part)[i] = 0.0f;
    if (tid == 0) g_count = 0u;

    __shared__ float sm[256];
    sm[tid] = acc;
    __syncthreads();
    #pragma unroll
    for (int s = 128; s > 0; s >>= 1) {
        if (tid < s) sm[tid] += sm[tid + s];
        __syncthreads();
    }
    if (tid == 0) out[0] = -sm[0] / (float)rows;
}

extern "C" void kernel_launch(void* const* d_in, const int* in_sizes, int n_in,
                              void* d_out, int out_size) {
    const float* x = (const float*)d_in[0];
    int rows = in_sizes[0] / COLS;   // 65536
    dim3 grid(GRID_X, GRID_Y);
    el_fused_kernel<<<grid, 256>>>(x, (float*)d_out, rows);
}

// round 5
// speedup vs baseline: 1.4530x; 1.4530x over previous
#include <cuda_runtime.h>
#include <math.h>

// EntropyLoss: x [R=65536, C=1024] f32 row-major.
//   n_j  = max( sqrt(sum_i x_ij^2), 1e-12 )
//   out  = -(1/R) * sum_j (1/n_j) * [ sum_i x*ln(x) - ln(n_j) * sum_i x ]
// (eps=1e-8 inside the reference log contributes <1e-6 relative error; dropped)
//
// Single fused launch. Mainloop is the validated R3 form (plain loads,
// pragma unroll, direct indexing — ptxas front-batches these itself; manual
// register batching in R4 serialized the loads and regressed 50->73us).
// Last block combines columns -> scalar, writes out, re-zeros scratch so
// every graph replay starts clean (globals are zero-init at module load).

#define COLS 1024
#define GRID_X 296          // row-chunks
#define GRID_Y 4            // column tiles of 256
#define NBLOCKS (GRID_X * GRID_Y)
#define LN2 0.6931471805599453f

__device__ float g_part[3][COLS];      // [0]=sum x^2, [1]=sum x, [2]=sum x*log2(x)
__device__ unsigned int g_count;

__global__ __launch_bounds__(256) void el_fused_kernel(const float* __restrict__ x,
                                                       float* __restrict__ out,
                                                       int rows) {
    const int tid     = threadIdx.x;
    const int cg      = tid & 63;     // 64 float4 column-groups per block (256 cols)
    const int slice   = tid >> 6;     // 4 row slices per block
    const int colbase = blockIdx.y * 256;
    const int g4      = (colbase >> 2) + cg;   // float4 index within a row

    const float4* __restrict__ p = (const float4*)x;

    float s2[4] = {0.f, 0.f, 0.f, 0.f};
    float s1[4] = {0.f, 0.f, 0.f, 0.f};
    float sx[4] = {0.f, 0.f, 0.f, 0.f};

    const int rstride = GRID_X * 4;
    #pragma unroll 4
    for (int r = blockIdx.x * 4 + slice; r < rows; r += rstride) {
        float4 v = p[(long)r * (COLS / 4) + g4];
        float vv[4] = {v.x, v.y, v.z, v.w};
        #pragma unroll
        for (int k = 0; k < 4; k++) {
            float a = vv[k];
            s2[k] = fmaf(a, a, s2[k]);
            s1[k] += a;
            // x*log2(x): at a==0 this is fmaf(0, lg2(1e-37), s) == s (correct limit)
            float l = __log2f(fmaxf(a, 1e-37f));
            sx[k] = fmaf(a, l, sx[k]);
        }
    }

    // Reduce the 4 row-slices within the block before touching L2 atomics.
    __shared__ float red[4][64 * 12];
    #pragma unroll
    for (int k = 0; k < 4; k++) {
        red[slice][cg * 12 + 0 + k] = s2[k];
        red[slice][cg * 12 + 4 + k] = s1[k];
        red[slice][cg * 12 + 8 + k] = sx[k];
    }
    __syncthreads();

    for (int i = tid; i < 64 * 12; i += 256) {
        float t = red[0][i] + red[1][i] + red[2][i] + red[3][i];
        int cg2  = i / 12;
        int comp = i % 12;
        int type = comp >> 2;     // 0: x^2, 1: x, 2: x*log2(x)
        int sub  = comp & 3;
        int col  = colbase + cg2 * 4 + sub;
        atomicAdd(&g_part[type][col], t);
    }

    // ---- last block does the final combine ----
    __shared__ int amLast;
    __threadfence();
    __syncthreads();
    if (tid == 0) {
        unsigned v = atomicAdd(&g_count, 1u);
        amLast = (v == NBLOCKS - 1);
    }
    __syncthreads();
    if (!amLast) return;

    // 256 threads over 1024 columns (4 each), L2 reads (bypass possibly-stale L1)
    float acc = 0.f;
    #pragma unroll
    for (int m = 0; m < 4; m++) {
        int j  = tid + m * 256;
        float S2 = __ldcg(&g_part[0][j]);
        float S1 = __ldcg(&g_part[1][j]);
        float SX = __ldcg(&g_part[2][j]);
        float n  = fmaxf(sqrtf(S2), 1e-12f);
        acc += (SX * LN2 - S1 * logf(n)) / n;
    }

    // re-zero scratch for the next graph replay
    for (int i = tid; i < 3 * COLS; i += 256) ((float*)g_part)[i] = 0.0f;
    if (tid == 0) g_count = 0u;

    __shared__ float sm[256];
    sm[tid] = acc;
    __syncthreads();
    #pragma unroll
    for (int s = 128; s > 0; s >>= 1) {
        if (tid < s) sm[tid] += sm[tid + s];
        __syncthreads();
    }
    if (tid == 0) out[0] = -sm[0] / (float)rows;
}

extern "C" void kernel_launch(void* const* d_in, const int* in_sizes, int n_in,
                              void* d_out, int out_size) {
    const float* x = (const float*)d_in[0];
    int rows = in_sizes[0] / COLS;   // 65536
    dim3 grid(GRID_X, GRID_Y);
    el_fused_kernel<<<grid, 256>>>(x, (float*)d_out, rows);
}

// round 6
// speedup vs baseline: 1.5074x; 1.0374x over previous
#include <cuda_runtime.h>
#include <math.h>

// EntropyLoss: x [R=65536, C=1024] f32 row-major.
//   n_j  = max( sqrt(sum_i x_ij^2), 1e-12 )
//   out  = -(1/R) * sum_j (1/n_j) * [ sum_i x*ln(x) - ln(n_j) * sum_i x ]
// (eps=1e-8 inside the reference log contributes <1e-6 relative error; dropped)
//
// Single fused launch, one wave of 740 CTAs (5/SM). __launch_bounds__(256,5)
// raises the reg budget to ~48 so ptxas can front-batch the fixed-8 inner
// loop's loads (R4/R5 showed the 32-reg budget at 8 CTAs/SM serializes them).
// Last block combines columns -> scalar, writes out, re-zeros scratch so every
// graph replay starts clean (globals are zero-init at module load).

#define COLS 1024
#define GRID_X 185          // row-chunks  (185*4 = 740 CTAs = 5/SM, one wave)
#define GRID_Y 4            // column tiles of 256
#define NBLOCKS (GRID_X * GRID_Y)
#define LN2 0.6931471805599453f

__device__ float g_part[3][COLS];      // [0]=sum x^2, [1]=sum x, [2]=sum x*log2(x)
__device__ unsigned int g_count;

__global__ __launch_bounds__(256, 5) void el_fused_kernel(const float* __restrict__ x,
                                                          float* __restrict__ out,
                                                          int rows) {
    const int tid     = threadIdx.x;
    const int cg      = tid & 63;     // 64 float4 column-groups per block (256 cols)
    const int slice   = tid >> 6;     // 4 row slices per block
    const int colbase = blockIdx.y * 256;
    const int g4      = (colbase >> 2) + cg;   // float4 index within a row

    const float4* __restrict__ p = (const float4*)x;

    float s2[4] = {0.f, 0.f, 0.f, 0.f};
    float s1[4] = {0.f, 0.f, 0.f, 0.f};
    float sx[4] = {0.f, 0.f, 0.f, 0.f};

    const int  rstride = GRID_X * 4;                 // 740 row slices total
    const int  r0      = blockIdx.x * 4 + slice;
    const long step    = (long)rstride * (COLS / 4);
    const float4* __restrict__ q = p + (long)r0 * (COLS / 4) + g4;

    const int iters = (rows - r0 + rstride - 1) / rstride;   // ~88-89
    const int it8   = iters & ~7;

    for (int b = 0; b < it8; b += 8) {
        // fixed trip count of 8: ptxas fully unrolls and front-batches the
        // 8 independent float4 loads (plain loads, no cache-hint intrinsics)
        #pragma unroll
        for (int u = 0; u < 8; u++) {
            float4 v = q[(long)u * step];
            float vv[4] = {v.x, v.y, v.z, v.w};
            #pragma unroll
            for (int k = 0; k < 4; k++) {
                float a = vv[k];
                s2[k] = fmaf(a, a, s2[k]);
                s1[k] += a;
                // x*log2(x): at a==0 this is fmaf(0, lg2(1e-37), s) == s
                float l = __log2f(fmaxf(a, 1e-37f));
                sx[k] = fmaf(a, l, sx[k]);
            }
        }
        q += 8 * step;
    }
    for (int i = it8; i < iters; i++) {
        float4 v = *q;
        q += step;
        float vv[4] = {v.x, v.y, v.z, v.w};
        #pragma unroll
        for (int k = 0; k < 4; k++) {
            float a = vv[k];
            s2[k] = fmaf(a, a, s2[k]);
            s1[k] += a;
            float l = __log2f(fmaxf(a, 1e-37f));
            sx[k] = fmaf(a, l, sx[k]);
        }
    }

    // Reduce the 4 row-slices within the block before touching L2 atomics.
    __shared__ float red[4][64 * 12];
    #pragma unroll
    for (int k = 0; k < 4; k++) {
        red[slice][cg * 12 + 0 + k] = s2[k];
        red[slice][cg * 12 + 4 + k] = s1[k];
        red[slice][cg * 12 + 8 + k] = sx[k];
    }
    __syncthreads();

    for (int i = tid; i < 64 * 12; i += 256) {
        float t = red[0][i] + red[1][i] + red[2][i] + red[3][i];
        int cg2  = i / 12;
        int comp = i % 12;
        int type = comp >> 2;     // 0: x^2, 1: x, 2: x*log2(x)
        int sub  = comp & 3;
        int col  = colbase + cg2 * 4 + sub;
        atomicAdd(&g_part[type][col], t);
    }

    // ---- last block does the final combine ----
    __shared__ int amLast;
    __threadfence();
    __syncthreads();
    if (tid == 0) {
        unsigned v = atomicAdd(&g_count, 1u);
        amLast = (v == NBLOCKS - 1);
    }
    __syncthreads();
    if (!amLast) return;

    // 256 threads over 1024 columns (4 each), L2 reads (bypass possibly-stale L1)
    float acc = 0.f;
    #pragma unroll
    for (int m = 0; m < 4; m++) {
        int j  = tid + m * 256;
        float S2 = __ldcg(&g_part[0][j]);
        float S1 = __ldcg(&g_part[1][j]);
        float SX = __ldcg(&g_part[2][j]);
        float n  = fmaxf(sqrtf(S2), 1e-12f);
        acc += (SX * LN2 - S1 * logf(n)) / n;
    }

    // re-zero scratch for the next graph replay
    for (int i = tid; i < 3 * COLS; i += 256) ((float*)g_part)[i] = 0.0f;
    if (tid == 0) g_count = 0u;

    __shared__ float sm[256];
    sm[tid] = acc;
    __syncthreads();
    #pragma unroll
    for (int s = 128; s > 0; s >>= 1) {
        if (tid < s) sm[tid] += sm[tid + s];
        __syncthreads();
    }
    if (tid == 0) out[0] = -sm[0] / (float)rows;
}

extern "C" void kernel_launch(void* const* d_in, const int* in_sizes, int n_in,
                              void* d_out, int out_size) {
    const float* x = (const float*)d_in[0];
    int rows = in_sizes[0] / COLS;   // 65536
    dim3 grid(GRID_X, GRID_Y);
    el_fused_kernel<<<grid, 256>>>(x, (float*)d_out, rows);
}

// round 7
// speedup vs baseline: 1.5155x; 1.0054x over previous
#include <cuda_runtime.h>
#include <math.h>

// EntropyLoss: x [R=65536, C=1024] f32 row-major.
//   n_j  = max( sqrt(sum_i x_ij^2), 1e-12 )
//   out  = -(1/R) * sum_j (1/n_j) * [ sum_i x*ln(x) - ln(n_j) * sum_i x ]
// (eps=1e-8 inside the reference log contributes <1e-6 relative error; dropped)
//
// Single fused launch, 740 CTAs (5/SM). NEW in this round: per-column-tile
// WORK STEALING over 32-row chunks (prefetched grab hides the atomic), to kill
// the end-of-wave spread (R5/R6 showed DRAM% plateaus ~75% regardless of
// occupancy/MLP -> ragged single-wave tail suspected). Chunk = 8 independent
// front-batchable float4 loads per thread. Last block combines -> scalar,
// writes out, re-zeros all scratch for the next graph replay.

#define COLS 1024
#define GRID_X 185          // 185*4 = 740 CTAs = 5/SM, one wave
#define GRID_Y 4            // column tiles of 256
#define NBLOCKS (GRID_X * GRID_Y)
#define CHUNK_ROWS 32
#define LN2 0.6931471805599453f

__device__ float g_part[3][COLS];      // [0]=sum x^2, [1]=sum x, [2]=sum x*log2(x)
__device__ unsigned int g_count;
__device__ unsigned int g_work[GRID_Y];

__global__ __launch_bounds__(256, 5) void el_fused_kernel(const float* __restrict__ x,
                                                          float* __restrict__ out,
                                                          int rows) {
    const int tid     = threadIdx.x;
    const int cg      = tid & 63;     // 64 float4 column-groups (256 cols)
    const int slice   = tid >> 6;     // 4 row slices per block
    const int ty      = blockIdx.y;
    const int colbase = ty * 256;
    const int g4      = (colbase >> 2) + cg;

    const float4* __restrict__ p = (const float4*)x;

    float s2[4] = {0.f, 0.f, 0.f, 0.f};
    float s1[4] = {0.f, 0.f, 0.f, 0.f};
    float sx[4] = {0.f, 0.f, 0.f, 0.f};

    const int nchunks = (rows + CHUNK_ROWS - 1) / CHUNK_ROWS;   // 2048

    __shared__ unsigned int sh_chunk;
    if (tid == 0) sh_chunk = atomicAdd(&g_work[ty], 1u);

    for (;;) {
        __syncthreads();
        const unsigned int c = sh_chunk;
        __syncthreads();
        if (c >= (unsigned)nchunks) break;
        // prefetch the next chunk id; L2 atomic latency hides under compute
        if (tid == 0) sh_chunk = atomicAdd(&g_work[ty], 1u);

        const long base = (long)(c * CHUNK_ROWS + slice) * (COLS / 4) + g4;

        if ((int)(c + 1) * CHUNK_ROWS <= rows) {
            // full chunk: 8 independent loads, fully unrolled -> front-batched
            #pragma unroll
            for (int u = 0; u < 8; u++) {
                float4 v = p[base + (long)u * (4 * (COLS / 4))];
                float vv[4] = {v.x, v.y, v.z, v.w};
                #pragma unroll
                for (int k = 0; k < 4; k++) {
                    float a = vv[k];
                    s2[k] = fmaf(a, a, s2[k]);
                    s1[k] += a;
                    // x*log2(x): at a==0 -> fmaf(0, lg2(1e-37), s) == s
                    float l = __log2f(fmaxf(a, 1e-37f));
                    sx[k] = fmaf(a, l, sx[k]);
                }
            }
        } else {
            // ragged last chunk (not hit for rows=65536)
            #pragma unroll
            for (int u = 0; u < 8; u++) {
                int r = (int)c * CHUNK_ROWS + slice + 4 * u;
                if (r < rows) {
                    float4 v = p[(long)r * (COLS / 4) + g4];
                    float vv[4] = {v.x, v.y, v.z, v.w};
                    #pragma unroll
                    for (int k = 0; k < 4; k++) {
                        float a = vv[k];
                        s2[k] = fmaf(a, a, s2[k]);
                        s1[k] += a;
                        float l = __log2f(fmaxf(a, 1e-37f));
                        sx[k] = fmaf(a, l, sx[k]);
                    }
                }
            }
        }
    }

    // Reduce the 4 row-slices within the block before touching L2 atomics.
    __shared__ float red[4][64 * 12];
    #pragma unroll
    for (int k = 0; k < 4; k++) {
        red[slice][cg * 12 + 0 + k] = s2[k];
        red[slice][cg * 12 + 4 + k] = s1[k];
        red[slice][cg * 12 + 8 + k] = sx[k];
    }
    __syncthreads();

    for (int i = tid; i < 64 * 12; i += 256) {
        float t = red[0][i] + red[1][i] + red[2][i] + red[3][i];
        int cg2  = i / 12;
        int comp = i % 12;
        int type = comp >> 2;     // 0: x^2, 1: x, 2: x*log2(x)
        int sub  = comp & 3;
        int col  = colbase + cg2 * 4 + sub;
        atomicAdd(&g_part[type][col], t);
    }

    // ---- last block does the final combine ----
    __shared__ int amLast;
    __threadfence();
    __syncthreads();
    if (tid == 0) {
        unsigned v = atomicAdd(&g_count, 1u);
        amLast = (v == NBLOCKS - 1);
    }
    __syncthreads();
    if (!amLast) return;

    // 256 threads over 1024 columns (4 each), L2 reads (bypass stale L1)
    float acc = 0.f;
    #pragma unroll
    for (int m = 0; m < 4; m++) {
        int j  = tid + m * 256;
        float S2 = __ldcg(&g_part[0][j]);
        float S1 = __ldcg(&g_part[1][j]);
        float SX = __ldcg(&g_part[2][j]);
        float n  = fmaxf(sqrtf(S2), 1e-12f);
        acc += (SX * LN2 - S1 * logf(n)) / n;
    }

    // re-zero all scratch for the next graph replay
    for (int i = tid; i < 3 * COLS; i += 256) ((float*)g_part)[i] = 0.0f;
    if (tid == 0) g_count = 0u;
    if (tid < GRID_Y) g_work[tid] = 0u;

    __shared__ float sm[256];
    sm[tid] = acc;
    __syncthreads();
    #pragma unroll
    for (int s = 128; s > 0; s >>= 1) {
        if (tid < s) sm[tid] += sm[tid + s];
        __syncthreads();
    }
    if (tid == 0) out[0] = -sm[0] / (float)rows;
}

extern "C" void kernel_launch(void* const* d_in, const int* in_sizes, int n_in,
                              void* d_out, int out_size) {
    const float* x = (const float*)d_in[0];
    int rows = in_sizes[0] / COLS;   // 65536
    dim3 grid(GRID_X, GRID_Y);
    el_fused_kernel<<<grid, 256>>>(x, (float*)d_out, rows);
}